// round 6
// baseline (speedup 1.0000x reference)
#include <cuda_runtime.h>
#include <math.h>

#define H 1024
#define E 512
#define A 512
#define L 512
#define V 50257

#define NB 296            // 2 blocks/SM on 148-152 SMs -> all resident
#define NT 512            // 16 warps/block
#define NWARP 16
#define GWN (NB * NWARP)  // 4736 warps total

// P0 warp-unit layout (each unit = 2 rows)
#define GHH_UNITS   2048  // 4096 W_hh rows
#define ATTN_UNITS  256   // 512 attn rows
#define COMBP_UNITS 512   // 1024 comb emb/av rows

#define P1_BLOCKS 32      // 16 enc rows per block
#define NPART 64          // attn-apply partial slices
#define P2_BLOCKS 32      // 1024 comb rows, 2/warp
#define P3_BLOCKS 128     // 4096 gate rows, 2/warp

// ---------------- scratch (device globals) ----------------------------------
__device__ __align__(16) float g_scores[L];
__device__ __align__(16) float g_part[NPART * H];
__device__ __align__(16) float g_ghh[4 * H];
__device__ __align__(16) float g_xpart[H];
__device__ __align__(16) float g_x[H];
__device__ __align__(16) float g_gates[4 * H];
__device__ unsigned g_barcnt;
__device__ volatile unsigned g_bargen;

__device__ __forceinline__ float warp_sum(float v) {
#pragma unroll
    for (int o = 16; o > 0; o >>= 1) v += __shfl_down_sync(0xffffffffu, v, o);
    return v;
}

// grid-wide barrier: all NB blocks arrive; last resets count and bumps gen.
__device__ __forceinline__ void gsync() {
    __threadfence();
    __syncthreads();
    if (threadIdx.x == 0) {
        unsigned gen = g_bargen;
        if (atomicAdd(&g_barcnt, 1u) == NB - 1) {
            g_barcnt = 0;
            __threadfence();
            g_bargen = gen + 1;
        } else {
            while (g_bargen == gen) __nanosleep(32);
        }
        __threadfence();
    }
    __syncthreads();
}

__device__ __forceinline__ void fma4(float& s, float4 a, float4 c) {
    s += a.x * c.x + a.y * c.y + a.z * c.z + a.w * c.w;
}

__global__ __launch_bounds__(NT, 2) void fused_decoder(
        const int* __restrict__ word, const float* __restrict__ emb,
        const float* __restrict__ h0, const float* __restrict__ c0,
        const float* __restrict__ av, const float* __restrict__ enc,
        const float* __restrict__ attn_W, const float* __restrict__ attn_b,
        const float* __restrict__ comb_W, const float* __restrict__ comb_b,
        const float* __restrict__ W_ih, const float* __restrict__ W_hh,
        const float* __restrict__ b_ih, const float* __restrict__ b_hh,
        const float* __restrict__ out_W, const float* __restrict__ out_b,
        float* __restrict__ o_logits, float* __restrict__ o_h,
        float* __restrict__ o_c, float* __restrict__ o_attn) {
    __shared__ float sm[2048];
    __shared__ float sred[NWARP];
    int t = threadIdx.x, lane = t & 31, w = t >> 5, b = blockIdx.x;

    // ================= P0: all input-independent GEMV streams =================
    {
        long wrow = (long)word[0] * E;
        for (int i = t; i < 2048; i += NT)
            sm[i] = (i < E) ? emb[wrow + i]
                  : (i < E + H) ? h0[i - E] : av[i - E - H];
        __syncthreads();
        int gw = b * NWARP + w;
        const float4* vv = reinterpret_cast<const float4*>(sm);
        if (gw < GHH_UNITS) {
            // W_hh @ h0 : rows gw, gw+2048 ; vector = sm[512..1536) = f4[128..384)
            int r0 = gw, r1 = gw + GHH_UNITS;
            const float4* w0 = reinterpret_cast<const float4*>(W_hh) + (size_t)r0 * 256;
            const float4* w1 = reinterpret_cast<const float4*>(W_hh) + (size_t)r1 * 256;
            float s0 = 0.f, s1 = 0.f;
#pragma unroll
            for (int i = 0; i < 8; i++) {
                float4 a = __ldcs(&w0[lane + 32 * i]);
                float4 a2 = __ldcs(&w1[lane + 32 * i]);
                float4 c = vv[128 + lane + 32 * i];
                fma4(s0, a, c);
                fma4(s1, a2, c);
            }
            s0 = warp_sum(s0); s1 = warp_sum(s1);
            if (lane == 0) { g_ghh[r0] = s0; g_ghh[r1] = s1; }
        } else if (gw < GHH_UNITS + ATTN_UNITS) {
            // attn scores: rows u, u+256 ; vector = [emb,h0] = f4[0..384)
            int u = gw - GHH_UNITS;
            int r0 = u, r1 = u + ATTN_UNITS;
            const float4* w0 = reinterpret_cast<const float4*>(attn_W) + (size_t)r0 * 384;
            const float4* w1 = reinterpret_cast<const float4*>(attn_W) + (size_t)r1 * 384;
            float s0 = 0.f, s1 = 0.f;
#pragma unroll
            for (int i = 0; i < 12; i++) {
                float4 a = __ldcs(&w0[lane + 32 * i]);
                float4 a2 = __ldcs(&w1[lane + 32 * i]);
                float4 c = vv[lane + 32 * i];
                fma4(s0, a, c);
                fma4(s1, a2, c);
            }
            s0 = warp_sum(s0); s1 = warp_sum(s1);
            if (lane == 0) {
                g_scores[r0] = s0 + attn_b[r0];
                g_scores[r1] = s1 + attn_b[r1];
            }
        } else if (gw < GHH_UNITS + ATTN_UNITS + COMBP_UNITS) {
            // comb partial (emb cols f4[0,128) + av cols f4[384,512))
            int u = gw - GHH_UNITS - ATTN_UNITS;
            int r0 = u, r1 = u + COMBP_UNITS;
            const float4* w0 = reinterpret_cast<const float4*>(comb_W) + (size_t)r0 * 512;
            const float4* w1 = reinterpret_cast<const float4*>(comb_W) + (size_t)r1 * 512;
            float s0 = 0.f, s1 = 0.f;
#pragma unroll
            for (int i = 0; i < 4; i++) {
                float4 c = vv[lane + 32 * i];              // emb slice
                float4 c2 = vv[384 + lane + 32 * i];       // av slice
                float4 a = __ldcs(&w0[lane + 32 * i]);
                float4 a2 = __ldcs(&w1[lane + 32 * i]);
                float4 d = __ldcs(&w0[384 + lane + 32 * i]);
                float4 d2 = __ldcs(&w1[384 + lane + 32 * i]);
                fma4(s0, a, c);  fma4(s1, a2, c);
                fma4(s0, d, c2); fma4(s1, d2, c2);
            }
            s0 = warp_sum(s0); s1 = warp_sum(s1);
            if (lane == 0) { g_xpart[r0] = s0; g_xpart[r1] = s1; }
        }
    }
    gsync();

    // ================= P1: softmax (redundant) + attn apply ==================
    if (b < P1_BLOCKS) {
        float v = g_scores[t];
        float m = v;
#pragma unroll
        for (int o = 16; o > 0; o >>= 1) m = fmaxf(m, __shfl_xor_sync(0xffffffffu, m, o));
        if (lane == 0) sred[w] = m;
        __syncthreads();
        if (t == 0) {
            float mm = sred[0];
#pragma unroll
            for (int i = 1; i < NWARP; i++) mm = fmaxf(mm, sred[i]);
            sm[1024] = mm;
        }
        __syncthreads();
        float e = expf(v - sm[1024]);
        float su = e;
#pragma unroll
        for (int o = 16; o > 0; o >>= 1) su += __shfl_xor_sync(0xffffffffu, su, o);
        __syncthreads();
        if (lane == 0) sred[w] = su;
        __syncthreads();
        if (t == 0) {
            float ss = 0.f;
#pragma unroll
            for (int i = 0; i < NWARP; i++) ss += sred[i];
            sm[1025] = ss;
        }
        __syncthreads();
        float wt = e / sm[1025];
        sm[t] = wt;
        if (b == 0) o_attn[t] = wt;
        __syncthreads();
        // apply: 16 enc rows/block, thread -> (col f4, row half)
        int col = t & 255, half = t >> 8;
        int l0 = b * 16 + half * 8;
        const float4* e4 = reinterpret_cast<const float4*>(enc);
        float4 acc = make_float4(0.f, 0.f, 0.f, 0.f);
#pragma unroll
        for (int l = 0; l < 8; l++) {
            float wk = sm[l0 + l];
            float4 x = __ldcs(&e4[(size_t)(l0 + l) * 256 + col]);
            acc.x += wk * x.x; acc.y += wk * x.y;
            acc.z += wk * x.z; acc.w += wk * x.w;
        }
        reinterpret_cast<float4*>(g_part)[(b * 2 + half) * 256 + col] = acc;
    }
    gsync();

    // ================= P2: comb attn columns -> x =============================
    if (b < P2_BLOCKS) {
        if (t < 256) {
            float4 acc = make_float4(0.f, 0.f, 0.f, 0.f);
            const float4* p4 = reinterpret_cast<const float4*>(g_part);
#pragma unroll 8
            for (int p = 0; p < NPART; p++) {
                float4 x = p4[p * 256 + t];
                acc.x += x.x; acc.y += x.y; acc.z += x.z; acc.w += x.w;
            }
            reinterpret_cast<float4*>(sm)[t] = acc;
        }
        __syncthreads();
        int u = b * NWARP + w;                 // [0,512)
        int r0 = u, r1 = u + 512;
        const float4* w0 = reinterpret_cast<const float4*>(comb_W) + (size_t)r0 * 512 + 128;
        const float4* w1 = reinterpret_cast<const float4*>(comb_W) + (size_t)r1 * 512 + 128;
        const float4* vv = reinterpret_cast<const float4*>(sm);
        float s0 = 0.f, s1 = 0.f;
#pragma unroll
        for (int i = 0; i < 8; i++) {
            float4 a = __ldcs(&w0[lane + 32 * i]);
            float4 a2 = __ldcs(&w1[lane + 32 * i]);
            float4 c = vv[lane + 32 * i];
            fma4(s0, a, c);
            fma4(s1, a2, c);
        }
        s0 = warp_sum(s0); s1 = warp_sum(s1);
        if (lane == 0) {
            g_x[r0] = fmaxf(s0 + g_xpart[r0] + comb_b[r0], 0.f);
            g_x[r1] = fmaxf(s1 + g_xpart[r1] + comb_b[r1], 0.f);
        }
    }
    gsync();

    // ================= P3: gates_ih ==========================================
    if (b < P3_BLOCKS) {
        if (t < 256)
            reinterpret_cast<float4*>(sm)[t] = reinterpret_cast<const float4*>(g_x)[t];
        __syncthreads();
        int u = b * NWARP + w;                 // [0,2048)
        int r0 = u, r1 = u + 2048;
        const float4* w0 = reinterpret_cast<const float4*>(W_ih) + (size_t)r0 * 256;
        const float4* w1 = reinterpret_cast<const float4*>(W_ih) + (size_t)r1 * 256;
        const float4* vv = reinterpret_cast<const float4*>(sm);
        float s0 = 0.f, s1 = 0.f;
#pragma unroll
        for (int i = 0; i < 8; i++) {
            float4 a = __ldcs(&w0[lane + 32 * i]);
            float4 a2 = __ldcs(&w1[lane + 32 * i]);
            float4 c = vv[lane + 32 * i];
            fma4(s0, a, c);
            fma4(s1, a2, c);
        }
        s0 = warp_sum(s0); s1 = warp_sum(s1);
        if (lane == 0) {
            g_gates[r0] = s0 + g_ghh[r0] + b_ih[r0] + b_hh[r0];
            g_gates[r1] = s1 + g_ghh[r1] + b_ih[r1] + b_hh[r1];
        }
    }
    gsync();

    // ================= P4: LSTM (redundant per block) + P5: logits ============
    for (int k = t; k < H; k += NT) {
        float gi = g_gates[k];
        float gf = g_gates[H + k];
        float gg = g_gates[2 * H + k];
        float go = g_gates[3 * H + k];
        float si = 1.f / (1.f + expf(-gi));
        float sf = 1.f / (1.f + expf(-gf));
        float so = 1.f / (1.f + expf(-go));
        float cn = sf * c0[k] + si * tanhf(gg);
        float hn = so * tanhf(cn);
        sm[k] = hn;
        if (b == 0) { o_h[k] = hn; o_c[k] = cn; }
    }
    __syncthreads();

    const float4* sh4 = reinterpret_cast<const float4*>(sm);
    for (unsigned unit = b * NWARP + w; unit * 2 < V; unit += GWN) {
        int r0 = 2 * unit, r1 = r0 + 1;
        bool has1 = r1 < V;
        const float4* w0 = reinterpret_cast<const float4*>(out_W) + (size_t)r0 * 256;
        const float4* w1 = reinterpret_cast<const float4*>(out_W)
                           + (size_t)(has1 ? r1 : r0) * 256;
        float s0 = 0.f, s1 = 0.f;
#pragma unroll
        for (int i = 0; i < 8; i++) {
            float4 a = __ldcs(&w0[lane + 32 * i]);
            float4 a2 = __ldcs(&w1[lane + 32 * i]);
            float4 h = sh4[lane + 32 * i];
            fma4(s0, a, h);
            fma4(s1, a2, h);
        }
        s0 = warp_sum(s0); s1 = warp_sum(s1);
        if (lane == 0) {
            o_logits[r0] = s0 + out_b[r0];
            if (has1) o_logits[r1] = s1 + out_b[r1];
        }
    }
}

// ---------------- launch ----------------------------------------------------
extern "C" void kernel_launch(void* const* d_in, const int* in_sizes, int n_in,
                              void* d_out, int out_size) {
    (void)out_size;
    const int* word = (const int*)d_in[0];
    int k = (n_in >= 2 && in_sizes[1] == 1) ? 2 : 1;
    const float* av_emb  = (const float*)d_in[k + 0];
    const float* h0      = (const float*)d_in[k + 1];
    const float* c0      = (const float*)d_in[k + 2];
    const float* enc_out = (const float*)d_in[k + 3];
    const float* emb     = (const float*)d_in[k + 4];
    const float* attn_W  = (const float*)d_in[k + 5];
    const float* attn_b  = (const float*)d_in[k + 6];
    const float* comb_W  = (const float*)d_in[k + 7];
    const float* comb_b  = (const float*)d_in[k + 8];
    const float* W_ih    = (const float*)d_in[k + 9];
    const float* W_hh    = (const float*)d_in[k + 10];
    const float* b_ih    = (const float*)d_in[k + 11];
    const float* b_hh    = (const float*)d_in[k + 12];
    const float* out_W   = (const float*)d_in[k + 13];
    const float* out_b   = (const float*)d_in[k + 14];

    float* out = (float*)d_out;
    float* o_logits = out;              // [V]
    float* o_h      = out + V;          // [H]
    float* o_c      = out + V + H;      // [H]
    float* o_attn   = out + V + 2 * H;  // [L]

    fused_decoder<<<NB, NT>>>(word, emb, h0, c0, av_emb, enc_out,
                              attn_W, attn_b, comb_W, comb_b,
                              W_ih, W_hh, b_ih, b_hh, out_W, out_b,
                              o_logits, o_h, o_c, o_attn);
}